// round 11
// baseline (speedup 1.0000x reference)
#include <cuda_runtime.h>
#include <cstdint>

#define NN   100000
#define NE   3200000
#define INF  1433
#define HID  16
#define OUTF 7
#define SCAN_BLK 512
#define NSCAN ((NN + SCAN_BLK - 1) / SCAN_BLK)   // 196

typedef unsigned long long ull;

// ---- scratch (device globals: allocation-free) ----
__device__ int   g_idx64;
__device__ int   g_idx[2 * NE];
__device__ int   g_csr[NE];
__device__ int   g_cnt_src[NN];
__device__ int   g_cnt_dst[NN];
__device__ int   g_off[NN];
__device__ int   g_cur[NN];
__device__ int   g_bsum[NSCAN];
__device__ float g_ns[NN];
__device__ float g_nd[NN];
__device__ float g_x1[(size_t)NN * HID];   // RAW feat@W1 (ns applied in gather)
__device__ float g_x2[(size_t)NN * 8];     // (relu(h)*ns)@W2, padded to 8

// ---- streams/events for capture-fork ----
struct HxInit {
    cudaStream_t s2;
    cudaEvent_t  e0, e1;
    HxInit() {
        cudaStreamCreateWithFlags(&s2, cudaStreamNonBlocking);
        cudaEventCreateWithFlags(&e0, cudaEventDisableTiming);
        cudaEventCreateWithFlags(&e1, cudaEventDisableTiming);
    }
};
static HxInit g_hx;

// ---------------------------------------------------------------------------
__global__ void k_detect(const unsigned int* __restrict__ ei_words) {
    __shared__ unsigned int acc;
    if (threadIdx.x == 0) acc = 0u;
    __syncthreads();
    unsigned int v = ei_words[2 * threadIdx.x + 1];
    atomicOr(&acc, v);
    __syncthreads();
    if (threadIdx.x == 0) g_idx64 = (acc == 0u) ? 1 : 0;
}

__global__ void k_zero() {
    int i = blockIdx.x * blockDim.x + threadIdx.x;
    if (i < NN) { g_cnt_src[i] = 0; g_cnt_dst[i] = 0; }
}

__global__ void k_convcnt(const void* __restrict__ ei) {
    int e = blockIdx.x * blockDim.x + threadIdx.x;
    if (e >= NE) return;
    int s, d;
    if (g_idx64) {
        s = (int)((const long long*)ei)[e];
        d = (int)((const long long*)ei)[(size_t)NE + e];
    } else {
        s = ((const int*)ei)[e];
        d = ((const int*)ei)[NE + e];
    }
    g_idx[e] = s;
    g_idx[NE + e] = d;
    atomicAdd(&g_cnt_src[s], 1);
    atomicAdd(&g_cnt_dst[d], 1);
}

__global__ void k_norm() {
    int i = blockIdx.x * blockDim.x + threadIdx.x;
    if (i >= NN) return;
    g_ns[i] = rsqrtf(fmaxf((float)g_cnt_src[i], 1.0f));
    g_nd[i] = rsqrtf(fmaxf((float)g_cnt_dst[i], 1.0f));
}

__global__ void k_scan1() {
    __shared__ int s[SCAN_BLK];
    int tid = threadIdx.x;
    int i = blockIdx.x * SCAN_BLK + tid;
    int v = (i < NN) ? g_cnt_dst[i] : 0;
    s[tid] = v;
    __syncthreads();
    for (int o = 1; o < SCAN_BLK; o <<= 1) {
        int t = (tid >= o) ? s[tid - o] : 0;
        __syncthreads();
        s[tid] += t;
        __syncthreads();
    }
    if (i < NN) g_off[i] = s[tid] - v;
    if (tid == SCAN_BLK - 1) g_bsum[blockIdx.x] = s[tid];
}

__global__ void k_scan2() {
    __shared__ int s[SCAN_BLK];
    int tid = threadIdx.x;
    int v = (tid < NSCAN) ? g_bsum[tid] : 0;
    s[tid] = v;
    __syncthreads();
    for (int o = 1; o < SCAN_BLK; o <<= 1) {
        int t = (tid >= o) ? s[tid - o] : 0;
        __syncthreads();
        s[tid] += t;
        __syncthreads();
    }
    if (tid < NSCAN) g_bsum[tid] = s[tid] - v;
}

__global__ void k_scan3() {
    int i = blockIdx.x * SCAN_BLK + threadIdx.x;
    if (i >= NN) return;
    int o = g_off[i] + g_bsum[blockIdx.x];
    g_off[i] = o;
    g_cur[i] = o;
}

__global__ void k_fill() {
    int e = blockIdx.x * blockDim.x + threadIdx.x;
    if (e >= NE) return;
    int s = g_idx[e];
    int d = g_idx[NE + e];
    int pos = atomicAdd(&g_cur[d], 1);
    g_csr[pos] = s;
}

// ---------------------------------------------------------------------------
// gemm1 (R9-best form): x1_raw = feat @ W1
// Block = 4 warps = 128 rows; grid 782. Branch-free inner loop, block-staged
// W tile, FFMA2 accumulators. ns folded into gather.
// ---------------------------------------------------------------------------
__global__ void __launch_bounds__(128) k_gemm1(const float* __restrict__ feat,
                                               const float* __restrict__ W1) {
    __shared__ float tile[4][32][33];
    __shared__ float sW[32][16];
    const int tid  = threadIdx.x;
    const int warp = tid >> 5;
    const int lane = tid & 31;
    const int r0 = (blockIdx.x * 4 + warp) * 32;

    ull acc[8];
#pragma unroll
    for (int j = 0; j < 8; j++) acc[j] = 0ULL;

    float (*t)[33] = tile[warp];

    for (int k0 = 0; k0 < INF; k0 += 32) {
        const int k = k0 + lane;
        const bool kok = (k < INF);
#pragma unroll 8
        for (int rr = 0; rr < 32; rr++) {
            const int r = min(r0 + rr, NN - 1);
            t[rr][lane] = kok ? feat[(size_t)r * INF + k] : 0.f;
        }
        {
#pragma unroll
            for (int q = 0; q < 4; q++) {
                const int i = tid + q * 128;
                const int kr = i >> 4, kc = i & 15;
                sW[kr][kc] = W1[(size_t)min(k0 + kr, INF - 1) * 16 + kc];
            }
        }
        __syncthreads();

#pragma unroll 8
        for (int kk = 0; kk < 32; kk++) {
            const float f = t[lane][kk];
            ull ff;
            asm("mov.b64 %0, {%1, %1};" : "=l"(ff) : "f"(f));
            const ull* wr = (const ull*)sW[kk];
            const ull w0 = wr[0], w1 = wr[1], w2 = wr[2], w3 = wr[3];
            const ull w4 = wr[4], w5 = wr[5], w6 = wr[6], w7 = wr[7];
            asm("fma.rn.f32x2 %0, %1, %2, %0;" : "+l"(acc[0]) : "l"(ff), "l"(w0));
            asm("fma.rn.f32x2 %0, %1, %2, %0;" : "+l"(acc[1]) : "l"(ff), "l"(w1));
            asm("fma.rn.f32x2 %0, %1, %2, %0;" : "+l"(acc[2]) : "l"(ff), "l"(w2));
            asm("fma.rn.f32x2 %0, %1, %2, %0;" : "+l"(acc[3]) : "l"(ff), "l"(w3));
            asm("fma.rn.f32x2 %0, %1, %2, %0;" : "+l"(acc[4]) : "l"(ff), "l"(w4));
            asm("fma.rn.f32x2 %0, %1, %2, %0;" : "+l"(acc[5]) : "l"(ff), "l"(w5));
            asm("fma.rn.f32x2 %0, %1, %2, %0;" : "+l"(acc[6]) : "l"(ff), "l"(w6));
            asm("fma.rn.f32x2 %0, %1, %2, %0;" : "+l"(acc[7]) : "l"(ff), "l"(w7));
        }
        __syncthreads();
    }

    const int myrow = r0 + lane;
    if (myrow < NN) {
        float o[16];
#pragma unroll
        for (int j = 0; j < 8; j++) {
            float lo, hi;
            asm("mov.b64 {%0, %1}, %2;" : "=f"(lo), "=f"(hi) : "l"(acc[j]));
            o[2 * j]     = lo;
            o[2 * j + 1] = hi;
        }
        float4* op = (float4*)(g_x1 + (size_t)myrow * 16);
#pragma unroll
        for (int c = 0; c < 4; c++)
            op[c] = make_float4(o[4 * c], o[4 * c + 1], o[4 * c + 2], o[4 * c + 3]);
    }
}

// ---------------------------------------------------------------------------
// fused gather1 + layer2: 16 lanes per node.
// lane j: m = sum_e ns[src]*x1_raw[src][j];  h = relu(m*nd+b1[j])*ns;
// then x2[node][j] (j<8) = sum_jj h_jj * W2[jj][j]  via 16 shfl+fma.
// ---------------------------------------------------------------------------
__global__ void __launch_bounds__(256) k_gatherL2(const float* __restrict__ b1,
                                                  const float* __restrict__ W2) {
    __shared__ float sW[16][8];     // W2 padded: col 7 -> 0
    const int tid = threadIdx.x;
    if (tid < 128) {
        const int jj = tid >> 3, j = tid & 7;
        sW[jj][j] = (j < 7) ? W2[jj * 7 + j] : 0.f;
    }
    __syncthreads();

    int t = blockIdx.x * blockDim.x + tid;
    int node = t >> 4;
    int j = t & 15;
    if (node >= NN) return;
    int beg = g_off[node];
    int end = beg + g_cnt_dst[node];
    float acc = 0.f;
#pragma unroll 4
    for (int e = beg; e < end; e++) {
        int s = g_csr[e];                          // broadcast across 16 lanes
        float nsv = g_ns[s];
        acc = fmaf(g_x1[(size_t)s * 16 + j], nsv, acc);
    }
    // h in lane j
    const float nd = g_nd[node];
    const float ns = g_ns[node];
    const float h = fmaxf(fmaf(acc, nd, __ldg(b1 + j)), 0.f) * ns;

    // 16x8 matvec across the 16-lane group; lane j produces column j (j<8 used)
    const int jc = j & 7;
    float o = 0.f;
#pragma unroll
    for (int jj = 0; jj < 16; jj++) {
        float hjj = __shfl_sync(0xFFFFFFFFu, h, (t & 16) | jj, 32); // own group
        o = fmaf(hjj, sW[jj][jc], o);
    }
    if (j < 8) g_x2[(size_t)node * 8 + j] = o;
}

// ---------------------------------------------------------------------------
// gather2 + epilogue: out[n,:7] = (sum x2[src]) * nd + b2 ; 8 lanes per node
// ---------------------------------------------------------------------------
__global__ void __launch_bounds__(256) k_gather2(float* __restrict__ out,
                                                 const float* __restrict__ b2) {
    int t = blockIdx.x * blockDim.x + threadIdx.x;
    int node = t >> 3;
    int j = t & 7;
    if (node >= NN) return;
    int beg = g_off[node];
    int end = beg + g_cnt_dst[node];
    float acc = 0.f;
#pragma unroll 4
    for (int e = beg; e < end; e++) {
        int s = g_csr[e];
        acc += g_x2[(size_t)s * 8 + j];
    }
    if (j < 7)
        out[(size_t)node * 7 + j] = fmaf(acc, g_nd[node], __ldg(b2 + j));
}

// ---------------------------------------------------------------------------
extern "C" void kernel_launch(void* const* d_in, const int* in_sizes, int n_in,
                              void* d_out, int out_size) {
    const float* feat = (const float*)d_in[0];
    const void*  ei   = d_in[1];
    const float* W1   = (const float*)d_in[2];
    const float* b1   = (const float*)d_in[3];
    const float* W2   = (const float*)d_in[4];
    const float* b2   = (const float*)d_in[5];
    float*       out  = (float*)d_out;

    // launches 1-3 (so gemm1 is our 4th launch -> ncu -s 5 captures it)
    k_detect<<<1, 32>>>((const unsigned int*)ei);
    k_zero<<<(NN + 255) / 256, 256>>>();
    k_convcnt<<<(NE + 255) / 256, 256>>>(ei);

    // fork: gemm1 concurrent with rest of CSR build
    cudaEventRecord(g_hx.e0, 0);
    cudaStreamWaitEvent(g_hx.s2, g_hx.e0, 0);
    k_gemm1<<<(NN + 127) / 128, 128, 0, g_hx.s2>>>(feat, W1);   // launch 4
    cudaEventRecord(g_hx.e1, g_hx.s2);

    k_norm<<<(NN + 255) / 256, 256>>>();
    k_scan1<<<NSCAN, SCAN_BLK>>>();
    k_scan2<<<1, SCAN_BLK>>>();
    k_scan3<<<NSCAN, SCAN_BLK>>>();
    k_fill<<<(NE + 255) / 256, 256>>>();

    // join: gather needs x1 + CSR
    cudaStreamWaitEvent(0, g_hx.e1, 0);
    k_gatherL2<<<(NN * 16 + 255) / 256, 256>>>(b1, W2);
    k_gather2<<<(NN * 8 + 255) / 256, 256>>>(out, b2);
}

// round 12
// speedup vs baseline: 1.2796x; 1.2796x over previous
#include <cuda_runtime.h>
#include <cstdint>

#define NN   100000
#define NE   3200000
#define INF  1433
#define HID  16
#define OUTF 7
#define SCAN_BLK 512
#define NSCAN ((NN + SCAN_BLK - 1) / SCAN_BLK)   // 196
#define NTILES 45            // ceil(1433/32)
#define SPLIT_T 23           // chunk0: tiles [0,23), chunk1: [23,45)

typedef unsigned long long ull;

// ---- scratch (device globals: allocation-free) ----
__device__ int   g_idx64;
__device__ int   g_idx[2 * NE];
__device__ int   g_csr[NE];
__device__ int   g_cnt_src[NN];
__device__ int   g_cnt_dst[NN];
__device__ int   g_off[NN];
__device__ int   g_cur[NN];
__device__ int   g_bsum[NSCAN];
__device__ float g_ns[NN];
__device__ float g_nd[NN];
__device__ float g_x1a[(size_t)NN * HID];  // K-chunk 0 partial
__device__ float g_x1b[(size_t)NN * HID];  // K-chunk 1 partial
__device__ float g_x1[(size_t)NN * HID];   // combined RAW feat@W1
__device__ float g_x2[(size_t)NN * 8];     // (relu(h)*ns)@W2, padded to 8

// ---- streams/events for capture-fork ----
struct HxInit {
    cudaStream_t s2;
    cudaEvent_t  e0, e1;
    HxInit() {
        cudaStreamCreateWithFlags(&s2, cudaStreamNonBlocking);
        cudaEventCreateWithFlags(&e0, cudaEventDisableTiming);
        cudaEventCreateWithFlags(&e1, cudaEventDisableTiming);
    }
};
static HxInit g_hx;

// ---------------------------------------------------------------------------
__global__ void k_detect(const unsigned int* __restrict__ ei_words) {
    __shared__ unsigned int acc;
    if (threadIdx.x == 0) acc = 0u;
    __syncthreads();
    unsigned int v = ei_words[2 * threadIdx.x + 1];
    atomicOr(&acc, v);
    __syncthreads();
    if (threadIdx.x == 0) g_idx64 = (acc == 0u) ? 1 : 0;
}

__global__ void k_zero() {
    int i = blockIdx.x * blockDim.x + threadIdx.x;
    if (i < NN) { g_cnt_src[i] = 0; g_cnt_dst[i] = 0; }
}

__global__ void k_convcnt(const void* __restrict__ ei) {
    int e = blockIdx.x * blockDim.x + threadIdx.x;
    if (e >= NE) return;
    int s, d;
    if (g_idx64) {
        s = (int)((const long long*)ei)[e];
        d = (int)((const long long*)ei)[(size_t)NE + e];
    } else {
        s = ((const int*)ei)[e];
        d = ((const int*)ei)[NE + e];
    }
    g_idx[e] = s;
    g_idx[NE + e] = d;
    atomicAdd(&g_cnt_src[s], 1);
    atomicAdd(&g_cnt_dst[d], 1);
}

__global__ void k_norm() {
    int i = blockIdx.x * blockDim.x + threadIdx.x;
    if (i >= NN) return;
    g_ns[i] = rsqrtf(fmaxf((float)g_cnt_src[i], 1.0f));
    g_nd[i] = rsqrtf(fmaxf((float)g_cnt_dst[i], 1.0f));
}

__global__ void k_scan1() {
    __shared__ int s[SCAN_BLK];
    int tid = threadIdx.x;
    int i = blockIdx.x * SCAN_BLK + tid;
    int v = (i < NN) ? g_cnt_dst[i] : 0;
    s[tid] = v;
    __syncthreads();
    for (int o = 1; o < SCAN_BLK; o <<= 1) {
        int t = (tid >= o) ? s[tid - o] : 0;
        __syncthreads();
        s[tid] += t;
        __syncthreads();
    }
    if (i < NN) g_off[i] = s[tid] - v;
    if (tid == SCAN_BLK - 1) g_bsum[blockIdx.x] = s[tid];
}

__global__ void k_scan2() {
    __shared__ int s[SCAN_BLK];
    int tid = threadIdx.x;
    int v = (tid < NSCAN) ? g_bsum[tid] : 0;
    s[tid] = v;
    __syncthreads();
    for (int o = 1; o < SCAN_BLK; o <<= 1) {
        int t = (tid >= o) ? s[tid - o] : 0;
        __syncthreads();
        s[tid] += t;
        __syncthreads();
    }
    if (tid < NSCAN) g_bsum[tid] = s[tid] - v;
}

__global__ void k_scan3() {
    int i = blockIdx.x * SCAN_BLK + threadIdx.x;
    if (i >= NN) return;
    int o = g_off[i] + g_bsum[blockIdx.x];
    g_off[i] = o;
    g_cur[i] = o;
}

__global__ void k_fill() {
    int e = blockIdx.x * blockDim.x + threadIdx.x;
    if (e >= NE) return;
    int s = g_idx[e];
    int d = g_idx[NE + e];
    int pos = atomicAdd(&g_cur[d], 1);
    g_csr[pos] = s;
}

// ---------------------------------------------------------------------------
// gemm1, K-split x2: even blocks do K-tiles [0,23), odd blocks [23,45).
// Block = 4 warps = 128 rows; grid = 2*782 = 1564 -> ~2x occupancy.
// Branch-free inner loop, block-staged W tile, FFMA2 accumulators.
// ---------------------------------------------------------------------------
__global__ void __launch_bounds__(128) k_gemm1(const float* __restrict__ feat,
                                               const float* __restrict__ W1) {
    __shared__ float tile[4][32][33];
    __shared__ float sW[32][16];
    const int tid  = threadIdx.x;
    const int warp = tid >> 5;
    const int lane = tid & 31;
    const int rb    = blockIdx.x >> 1;
    const int chunk = blockIdx.x & 1;
    const int r0 = (rb * 4 + warp) * 32;
    const int t0 = chunk ? SPLIT_T : 0;
    const int t1 = chunk ? NTILES : SPLIT_T;

    ull acc[8];
#pragma unroll
    for (int j = 0; j < 8; j++) acc[j] = 0ULL;

    float (*t)[33] = tile[warp];

    for (int kt = t0; kt < t1; kt++) {
        const int k0 = kt * 32;
        const int k = k0 + lane;
        const bool kok = (k < INF);
#pragma unroll 8
        for (int rr = 0; rr < 32; rr++) {
            const int r = min(r0 + rr, NN - 1);
            t[rr][lane] = kok ? feat[(size_t)r * INF + k] : 0.f;
        }
        {
#pragma unroll
            for (int q = 0; q < 4; q++) {
                const int i = tid + q * 128;
                const int kr = i >> 4, kc = i & 15;
                sW[kr][kc] = W1[(size_t)min(k0 + kr, INF - 1) * 16 + kc];
            }
        }
        __syncthreads();

#pragma unroll 8
        for (int kk = 0; kk < 32; kk++) {
            const float f = t[lane][kk];
            ull ff;
            asm("mov.b64 %0, {%1, %1};" : "=l"(ff) : "f"(f));
            const ull* wr = (const ull*)sW[kk];
            const ull w0 = wr[0], w1 = wr[1], w2 = wr[2], w3 = wr[3];
            const ull w4 = wr[4], w5 = wr[5], w6 = wr[6], w7 = wr[7];
            asm("fma.rn.f32x2 %0, %1, %2, %0;" : "+l"(acc[0]) : "l"(ff), "l"(w0));
            asm("fma.rn.f32x2 %0, %1, %2, %0;" : "+l"(acc[1]) : "l"(ff), "l"(w1));
            asm("fma.rn.f32x2 %0, %1, %2, %0;" : "+l"(acc[2]) : "l"(ff), "l"(w2));
            asm("fma.rn.f32x2 %0, %1, %2, %0;" : "+l"(acc[3]) : "l"(ff), "l"(w3));
            asm("fma.rn.f32x2 %0, %1, %2, %0;" : "+l"(acc[4]) : "l"(ff), "l"(w4));
            asm("fma.rn.f32x2 %0, %1, %2, %0;" : "+l"(acc[5]) : "l"(ff), "l"(w5));
            asm("fma.rn.f32x2 %0, %1, %2, %0;" : "+l"(acc[6]) : "l"(ff), "l"(w6));
            asm("fma.rn.f32x2 %0, %1, %2, %0;" : "+l"(acc[7]) : "l"(ff), "l"(w7));
        }
        __syncthreads();
    }

    const int myrow = r0 + lane;
    if (myrow < NN) {
        float* xout = chunk ? g_x1b : g_x1a;
        float o[16];
#pragma unroll
        for (int j = 0; j < 8; j++) {
            float lo, hi;
            asm("mov.b64 {%0, %1}, %2;" : "=f"(lo), "=f"(hi) : "l"(acc[j]));
            o[2 * j]     = lo;
            o[2 * j + 1] = hi;
        }
        float4* op = (float4*)(xout + (size_t)myrow * 16);
#pragma unroll
        for (int c = 0; c < 4; c++)
            op[c] = make_float4(o[4 * c], o[4 * c + 1], o[4 * c + 2], o[4 * c + 3]);
    }
}

// combine the two K-chunk partials: x1 = x1a + x1b  (float4)
__global__ void k_combine() {
    int i = blockIdx.x * blockDim.x + threadIdx.x;
    if (i >= NN * HID / 4) return;
    const float4 a = ((const float4*)g_x1a)[i];
    const float4 b = ((const float4*)g_x1b)[i];
    ((float4*)g_x1)[i] = make_float4(a.x + b.x, a.y + b.y, a.z + b.z, a.w + b.w);
}

// ---------------------------------------------------------------------------
// fused gather1 + layer2: 16 lanes per node.
// ---------------------------------------------------------------------------
__global__ void __launch_bounds__(256) k_gatherL2(const float* __restrict__ b1,
                                                  const float* __restrict__ W2) {
    __shared__ float sW[16][8];     // W2 padded: col 7 -> 0
    const int tid = threadIdx.x;
    if (tid < 128) {
        const int jj = tid >> 3, j = tid & 7;
        sW[jj][j] = (j < 7) ? W2[jj * 7 + j] : 0.f;
    }
    __syncthreads();

    int t = blockIdx.x * blockDim.x + tid;
    int node = t >> 4;
    int j = t & 15;
    if (node >= NN) return;
    int beg = g_off[node];
    int end = beg + g_cnt_dst[node];
    float acc = 0.f;
#pragma unroll 4
    for (int e = beg; e < end; e++) {
        int s = g_csr[e];
        float nsv = g_ns[s];
        acc = fmaf(g_x1[(size_t)s * 16 + j], nsv, acc);
    }
    const float nd = g_nd[node];
    const float ns = g_ns[node];
    const float h = fmaxf(fmaf(acc, nd, __ldg(b1 + j)), 0.f) * ns;

    const int jc = j & 7;
    float o = 0.f;
#pragma unroll
    for (int jj = 0; jj < 16; jj++) {
        float hjj = __shfl_sync(0xFFFFFFFFu, h, (t & 16) | jj, 32);
        o = fmaf(hjj, sW[jj][jc], o);
    }
    if (j < 8) g_x2[(size_t)node * 8 + j] = o;
}

// ---------------------------------------------------------------------------
// gather2 + epilogue: out[n,:7] = (sum x2[src]) * nd + b2 ; 8 lanes per node
// ---------------------------------------------------------------------------
__global__ void __launch_bounds__(256) k_gather2(float* __restrict__ out,
                                                 const float* __restrict__ b2) {
    int t = blockIdx.x * blockDim.x + threadIdx.x;
    int node = t >> 3;
    int j = t & 7;
    if (node >= NN) return;
    int beg = g_off[node];
    int end = beg + g_cnt_dst[node];
    float acc = 0.f;
#pragma unroll 4
    for (int e = beg; e < end; e++) {
        int s = g_csr[e];
        acc += g_x2[(size_t)s * 8 + j];
    }
    if (j < 7)
        out[(size_t)node * 7 + j] = fmaf(acc, g_nd[node], __ldg(b2 + j));
}

// ---------------------------------------------------------------------------
extern "C" void kernel_launch(void* const* d_in, const int* in_sizes, int n_in,
                              void* d_out, int out_size) {
    const float* feat = (const float*)d_in[0];
    const void*  ei   = d_in[1];
    const float* W1   = (const float*)d_in[2];
    const float* b1   = (const float*)d_in[3];
    const float* W2   = (const float*)d_in[4];
    const float* b2   = (const float*)d_in[5];
    float*       out  = (float*)d_out;

    // allow max smem carveout so ~11 blocks of 19KB can co-reside
    static bool attr_done = false;
    if (!attr_done) {
        cudaFuncSetAttribute(k_gemm1,
            cudaFuncAttributePreferredSharedMemoryCarveout, 100);
        attr_done = true;
    }

    // fork FIRST: gemm1 (independent of edges) runs under the CSR build
    cudaEventRecord(g_hx.e0, 0);
    cudaStreamWaitEvent(g_hx.s2, g_hx.e0, 0);
    k_gemm1<<<2 * ((NN + 127) / 128), 128, 0, g_hx.s2>>>(feat, W1);
    k_combine<<<(NN * HID / 4 + 255) / 256, 256, 0, g_hx.s2>>>();
    cudaEventRecord(g_hx.e1, g_hx.s2);

    // main stream: CSR build
    k_detect<<<1, 32>>>((const unsigned int*)ei);
    k_zero<<<(NN + 255) / 256, 256>>>();
    k_convcnt<<<(NE + 255) / 256, 256>>>(ei);
    k_norm<<<(NN + 255) / 256, 256>>>();
    k_scan1<<<NSCAN, SCAN_BLK>>>();
    k_scan2<<<1, SCAN_BLK>>>();
    k_scan3<<<NSCAN, SCAN_BLK>>>();
    k_fill<<<(NE + 255) / 256, 256>>>();

    // join: gather needs x1 + CSR
    cudaStreamWaitEvent(0, g_hx.e1, 0);
    k_gatherL2<<<(NN * 16 + 255) / 256, 256>>>(b1, W2);
    k_gather2<<<(NN * 8 + 255) / 256, 256>>>(out, b2);
}